// round 15
// baseline (speedup 1.0000x reference)
#include <cuda_runtime.h>
#include <cuda_bf16.h>

#define SEQ 2048
#define DIM 1024
#define NH 16
#define HDIM 64
#define SCALE 0.125f
#define ENTW 0.5f
#define DECAYC 0.1f
#define SUPW 0.3f
#define LNEPS 1e-5f
#define PI_F 3.14159265358979323846f

// ---------------- scratch ----------------
__device__ float g_v[SEQ * DIM];
__device__ float g_res[SEQ * DIM];
__device__ float g_ca[SEQ * NH];
__device__ float g_sa[SEQ * NH];
__device__ __nv_bfloat16 g_qb[SEQ * DIM];
__device__ __nv_bfloat16 g_kb[SEQ * DIM];
__device__ __nv_bfloat16 g_eqb[SEQ * DIM];
__device__ __nv_bfloat16 g_ekb[SEQ * DIM];
__device__ __nv_bfloat16 g_ab[SEQ * DIM];          // activations (hs, then ctx)
__device__ __nv_bfloat16 g_wb[6 * DIM * DIM];      // weights bf16
__device__ __nv_bfloat16 g_mxT[DIM * SEQ];         // mixed, transposed [h*64+d][s]

// ---------------- helpers ----------------
__device__ __forceinline__ unsigned smem_u32(const void* p) {
    unsigned a;
    asm("{ .reg .u64 t; cvta.to.shared.u64 t, %1; cvt.u32.u64 %0, t; }" : "=r"(a) : "l"(p));
    return a;
}
__device__ __forceinline__ void cp16(unsigned d, const void* s) {
    asm volatile("cp.async.cg.shared.global [%0], [%1], 16;" :: "r"(d), "l"(s));
}
__device__ __forceinline__ void ldm4(unsigned* r, unsigned a) {
    asm volatile("ldmatrix.sync.aligned.m8n8.x4.shared.b16 {%0,%1,%2,%3}, [%4];"
        : "=r"(r[0]), "=r"(r[1]), "=r"(r[2]), "=r"(r[3]) : "r"(a));
}
__device__ __forceinline__ void mmabf(float* d, const unsigned* a, const unsigned* b) {
    asm volatile(
        "mma.sync.aligned.m16n8k16.row.col.f32.bf16.bf16.f32 "
        "{%0,%1,%2,%3}, {%4,%5,%6,%7}, {%8,%9}, {%0,%1,%2,%3};"
        : "+f"(d[0]), "+f"(d[1]), "+f"(d[2]), "+f"(d[3])
        : "r"(a[0]), "r"(a[1]), "r"(a[2]), "r"(a[3]), "r"(b[0]), "r"(b[1]));
}

// ---------------- fp32 -> bf16 conversions ----------------
__global__ __launch_bounds__(256) void k_cvt1(const float* __restrict__ s,
                                              __nv_bfloat16* __restrict__ o, int n4) {
    int i = blockIdx.x * 256 + threadIdx.x;
    if (i >= n4) return;
    float4 x = ((const float4*)s)[i];
    __nv_bfloat162 a, b;
    a.x = __float2bfloat16(x.x); a.y = __float2bfloat16(x.y);
    b.x = __float2bfloat16(x.z); b.y = __float2bfloat16(x.w);
    ((__nv_bfloat162*)o)[i * 2] = a;
    ((__nv_bfloat162*)o)[i * 2 + 1] = b;
}

__global__ __launch_bounds__(256) void k_cvtw(
        const float* __restrict__ w0, const float* __restrict__ w1,
        const float* __restrict__ w2, const float* __restrict__ w3,
        const float* __restrict__ w4, const float* __restrict__ w5,
        __nv_bfloat16* __restrict__ o) {
    const float* src;
    switch (blockIdx.y) {
        case 0: src = w0; break;
        case 1: src = w1; break;
        case 2: src = w2; break;
        case 3: src = w3; break;
        case 4: src = w4; break;
        default: src = w5; break;
    }
    int i = blockIdx.x * 256 + threadIdx.x;
    float4 x = ((const float4*)src)[i];
    __nv_bfloat16* op = o + (size_t)blockIdx.y * DIM * DIM;
    __nv_bfloat162 a, b;
    a.x = __float2bfloat16(x.x); a.y = __float2bfloat16(x.y);
    b.x = __float2bfloat16(x.z); b.y = __float2bfloat16(x.w);
    ((__nv_bfloat162*)op)[i * 2] = a;
    ((__nv_bfloat162*)op)[i * 2 + 1] = b;
}

// ---------------- bf16 mma GEMM: 128 thr / 4 warps, warp tile 64x64 ----------------
#define RSTR 40
#define PLANE 10240
#define STAGE (2 * PLANE)
#define GSMEM (3 * STAGE)          // 61440 B

__device__ __forceinline__ void load_chunk(unsigned st,
        const __nv_bfloat16* __restrict__ A, const __nv_bfloat16* __restrict__ B,
        int m0, int n0, int k0, int tid) {
#pragma unroll
    for (int i = 0; i < 8; i++) {
        int idx = i * 128 + tid;           // 0..1023
        int plane = idx >> 9;
        int row = (idx >> 2) & 127;
        int ck = idx & 3;
        unsigned soff = st + plane * PLANE + (unsigned)(row * RSTR + ck * 8) * 2;
        const __nv_bfloat16* gp = plane
            ? (B + (size_t)(n0 + row) * DIM + k0 + ck * 8)
            : (A + (size_t)(m0 + row) * DIM + k0 + ck * 8);
        cp16(soff, gp);
    }
    asm volatile("cp.async.commit_group;" ::: "memory");
}

__device__ __forceinline__ void gemm_mma(
        const __nv_bfloat16* __restrict__ A, const __nv_bfloat16* __restrict__ W,
        const float* __restrict__ bias, const float* __restrict__ resid,
        float* __restrict__ Cf, __nv_bfloat16* __restrict__ Cb) {
    extern __shared__ char dynsm[];
    unsigned sb = smem_u32(dynsm);
    int tid = threadIdx.x, lane = tid & 31, w = tid >> 5;
    int wm = w & 1, wn = w >> 1;               // 2 x 2 warps, warp tile 64x64
    int m0 = blockIdx.y * 128, n0 = blockIdx.x * 128;

    float acc[4][8][4];
#pragma unroll
    for (int a = 0; a < 4; a++)
#pragma unroll
        for (int b = 0; b < 8; b++)
#pragma unroll
            for (int d = 0; d < 4; d++) acc[a][b][d] = 0.f;

    load_chunk(sb,          A, W, m0, n0, 0, tid);
    load_chunk(sb + STAGE,  A, W, m0, n0, 32, tid);

    int lrA = lane & 15;
    int lcA = (lane >> 4) << 3;
    int lnB = (lane & 7) + ((lane >> 4) << 3);
    int lkB = ((lane >> 3) & 1) << 3;
    unsigned aRow = (unsigned)((wm * 64 + lrA) * RSTR) * 2;
    unsigned bRow = (unsigned)((wn * 64 + lnB) * RSTR) * 2;

    int sidx = 0;
    for (int c = 0; c < 32; c++) {
        if (c < 31) asm volatile("cp.async.wait_group 1;" ::: "memory");
        else        asm volatile("cp.async.wait_group 0;" ::: "memory");
        __syncthreads();
        if (c + 2 < 32) {
            int s2i = sidx + 2; if (s2i >= 3) s2i -= 3;
            load_chunk(sb + s2i * STAGE, A, W, m0, n0, (c + 2) * 32, tid);
        }
        unsigned st = sb + sidx * STAGE;
#pragma unroll
        for (int ks = 0; ks < 32; ks += 16) {
            unsigned ah[4][4], bh[8][2];
#pragma unroll
            for (int mt = 0; mt < 4; mt++)
                ldm4(ah[mt], st + aRow + (unsigned)(mt * 16 * RSTR + ks + lcA) * 2);
#pragma unroll
            for (int p = 0; p < 4; p++) {
                unsigned t[4];
                ldm4(t, st + PLANE + bRow + (unsigned)(p * 16 * RSTR + ks + lkB) * 2);
                bh[2 * p][0] = t[0]; bh[2 * p][1] = t[1];
                bh[2 * p + 1][0] = t[2]; bh[2 * p + 1][1] = t[3];
            }
#pragma unroll
            for (int mt = 0; mt < 4; mt++)
#pragma unroll
                for (int nt = 0; nt < 8; nt++)
                    mmabf(acc[mt][nt], ah[mt], bh[nt]);
        }
        if (++sidx == 3) sidx = 0;
    }

    int r0 = m0 + wm * 64 + (lane >> 2);
    int cb = n0 + wn * 64 + (lane & 3) * 2;
#pragma unroll
    for (int mt = 0; mt < 4; mt++) {
#pragma unroll
        for (int nt = 0; nt < 8; nt++) {
            int rr = r0 + mt * 16;
            int cc = cb + nt * 8;
            float b0 = bias[cc], b1 = bias[cc + 1];
            float2 v0 = make_float2(acc[mt][nt][0] + b0, acc[mt][nt][1] + b1);
            float2 v1 = make_float2(acc[mt][nt][2] + b0, acc[mt][nt][3] + b1);
            if (resid) {
                const float2 q0 = *(const float2*)(resid + (size_t)rr * DIM + cc);
                const float2 q1 = *(const float2*)(resid + (size_t)(rr + 8) * DIM + cc);
                v0.x += q0.x; v0.y += q0.y;
                v1.x += q1.x; v1.y += q1.y;
            }
            if (Cb) {
                __nv_bfloat162 o0, o1;
                o0.x = __float2bfloat16(v0.x); o0.y = __float2bfloat16(v0.y);
                o1.x = __float2bfloat16(v1.x); o1.y = __float2bfloat16(v1.y);
                *(__nv_bfloat162*)(Cb + (size_t)rr * DIM + cc) = o0;
                *(__nv_bfloat162*)(Cb + (size_t)(rr + 8) * DIM + cc) = o1;
            } else {
                *(float2*)(Cf + (size_t)rr * DIM + cc) = v0;
                *(float2*)(Cf + (size_t)(rr + 8) * DIM + cc) = v1;
            }
        }
    }
}

// V projection alone (unblocks the mixer early)
__global__ __launch_bounds__(128) void k_projv(const float* __restrict__ bv) {
    gemm_mma(g_ab, g_wb + 2ull * DIM * DIM, bv, nullptr, g_v, nullptr);
}

// remaining 4 projections: z -> {Wq, Wk, Weq, Wek}
__global__ __launch_bounds__(128) void k_proj4(
        const float* __restrict__ bq, const float* __restrict__ bk,
        const float* __restrict__ beq, const float* __restrict__ bek) {
    int z = blockIdx.z;
    const float* bias; __nv_bfloat16* Cb; int widx;
    switch (z) {
        case 0:  bias = bq;  Cb = g_qb;  widx = 0; break;
        case 1:  bias = bk;  Cb = g_kb;  widx = 1; break;
        case 2:  bias = beq; Cb = g_eqb; widx = 3; break;
        default: bias = bek; Cb = g_ekb; widx = 4; break;
    }
    gemm_mma(g_ab, g_wb + (size_t)widx * DIM * DIM, bias, nullptr, nullptr, Cb);
}

__global__ __launch_bounds__(128) void k_wo(const float* __restrict__ bo,
                                            const float* __restrict__ hs) {
    gemm_mma(g_ab, g_wb + 5ull * DIM * DIM, bo, hs, g_res, nullptr);
}

// ---------------- K2: amplitudes & phases ----------------
__global__ __launch_bounds__(256) void k_ampph(const float* __restrict__ hs,
                                               const float* __restrict__ aw,
                                               const float* __restrict__ ab,
                                               const float* __restrict__ pw,
                                               const float* __restrict__ pb) {
    __shared__ float row[DIM];
    __shared__ float acc[32];
    int s = blockIdx.x, tid = threadIdx.x;
    for (int i = tid; i < DIM; i += 256) row[i] = hs[(size_t)s * DIM + i];
    __syncthreads();
    int w = tid >> 5, lane = tid & 31;
#pragma unroll
    for (int t = 0; t < 4; t++) {
        int o = w * 4 + t;
        int hh = o & 15;
        const float* wp = (o < 16) ? (aw + (size_t)hh * DIM) : (pw + (size_t)hh * DIM);
        float sum = 0.f;
        for (int i = lane; i < DIM; i += 32) sum += row[i] * wp[i];
#pragma unroll
        for (int m = 16; m; m >>= 1) sum += __shfl_xor_sync(0xffffffffu, sum, m);
        if (lane == 0) acc[o] = sum + ((o < 16) ? ab[hh] : pb[hh]);
    }
    __syncthreads();
    if (tid < NH) {
        float a = 1.f / (1.f + expf(-acc[tid]));
        float ph = tanhf(acc[16 + tid]) * PI_F;
        float sp, cp;
        sincosf(ph, &sp, &cp);
        g_ca[s * NH + tid] = SUPW * a * cp;
        g_sa[s * NH + tid] = SUPW * a * sp;
    }
}

// ---------------- K3: superposition mixer -> g_mxT ----------------
__global__ __launch_bounds__(256) void k_mixed(const float* __restrict__ mw_g,
                                               const float* __restrict__ mb_g) {
    __shared__ float mw[64][65];
    __shared__ float vt[32][65];
    __shared__ float sp[32][65];
    __shared__ float mb[64];
    int h = blockIdx.y, s0 = blockIdx.x * 32;
    int tid = threadIdx.x;
    for (int i = tid; i < 4096; i += 256) mw[i >> 6][i & 63] = mw_g[h * 4096 + i];
    if (tid < 64) mb[tid] = mb_g[h * 64 + tid];
    for (int i = tid; i < 2048; i += 256)
        vt[i >> 6][i & 63] = g_v[(size_t)(s0 + (i >> 6)) * DIM + h * HDIM + (i & 63)];
    __syncthreads();

    int r = tid >> 3;
    int ob = (tid & 7) * 8;
    float a[8];
#pragma unroll
    for (int j = 0; j < 8; j++) a[j] = 0.f;
    for (int d = 0; d < 64; d++) {
        float vv = vt[r][d];
#pragma unroll
        for (int j = 0; j < 8; j++) a[j] += vv * mw[ob + j][d];
    }
#pragma unroll
    for (int j = 0; j < 8; j++) sp[r][ob + j] = a[j] + mb[ob + j];
    __syncthreads();

    for (int i = tid; i < 2048; i += 256) {
        int d = i >> 5, sl = i & 31;
        float ca = g_ca[(s0 + sl) * NH + h];
        float sa = g_sa[(s0 + sl) * NH + h];
        float val = vt[sl][d] + ca * sp[sl][d] + sa * sp[sl][(d + 63) & 63];
        g_mxT[(size_t)(h * HDIM + d) * SEQ + s0 + sl] = __float2bfloat16(val);
    }
}

// ---------------- K4: FA2 attention, 4 CTAs/SM ----------------
#define STG_K 0
#define STG_M 9216
#define STG_F 18432
#define STG_SZ 27648
#define AO_D (2 * STG_SZ)
#define ATT_SMEM (2 * STG_SZ + 512)       // 55808

__device__ __forceinline__ void att_load(unsigned sb, int kt, int q0,
                                         size_t hoff, int tid) {
    int k0 = kt * 64;
    int dq = q0 - k0; int adq = dq < 0 ? -dq : dq;
    bool ent = (adq <= 384);
    unsigned st = sb + (kt & 1) * STG_SZ;
#pragma unroll
    for (int t = 0; t < 4; t++) {
        int idx = tid + t * 128;
        int row = idx >> 3, ck = idx & 7;
        cp16(st + STG_K + row * 144 + ck * 16,
             g_kb + (size_t)(k0 + row) * DIM + hoff + ck * 8);
        cp16(st + STG_M + row * 144 + ck * 16,
             g_mxT + (hoff + row) * SEQ + k0 + ck * 8);
        if (ent)
            cp16(st + STG_F + row * 144 + ck * 16,
                 g_ekb + (size_t)(k0 + row) * DIM + hoff + ck * 8);
    }
    asm volatile("cp.async.commit_group;" ::: "memory");
}

__global__ __launch_bounds__(128, 4) void k_attn_tc() {
    extern __shared__ __align__(16) char smc[];
    unsigned sb = smem_u32(smc);
    float* dtab = (float*)(smc + AO_D);

    int h = blockIdx.y, q0 = blockIdx.x * 64;
    int tid = threadIdx.x, lane = tid & 31, w = tid >> 5;
    size_t hoff = (size_t)h * HDIM;

    unsigned b1 = sb + STG_SZ;
#pragma unroll
    for (int t = 0; t < 4; t++) {
        int idx = tid + t * 128;
        int row = idx >> 3, ck = idx & 7;
        cp16(b1 + STG_K + row * 144 + ck * 16,
             g_qb + (size_t)(q0 + row) * DIM + hoff + ck * 8);
        cp16(b1 + STG_M + row * 144 + ck * 16,
             g_eqb + (size_t)(q0 + row) * DIM + hoff + ck * 8);
    }
    asm volatile("cp.async.commit_group;" ::: "memory");
    att_load(sb, 0, q0, hoff, tid);
    asm volatile("cp.async.wait_group 1;" ::: "memory");
    __syncthreads();

    unsigned aoff = (unsigned)((16 * w + (lane & 15)) * 144 + ((lane >> 4) << 4));
    unsigned qa[4][4], ea[4][4];
#pragma unroll
    for (int kf = 0; kf < 4; kf++) {
        ldm4(qa[kf], b1 + STG_K + aoff + kf * 32);
        ldm4(ea[kf], b1 + STG_M + aoff + kf * 32);
    }

    float m0 = -1e30f, m1 = -1e30f, l0 = 0.f, l1 = 0.f;
    float o[8][4];
#pragma unroll
    for (int j = 0; j < 8; j++)
#pragma unroll
        for (int e = 0; e < 4; e++) o[j][e] = 0.f;

    unsigned boff = (unsigned)(((lane & 7) + ((lane >> 4) << 3)) * 144 +
                               (((lane >> 3) & 1) << 4));
    int qr = (lane >> 2);
    int qc = (lane & 3) * 2;

    for (int kt = 0; kt < 32; kt++) {
        int k0 = kt * 64;
        int dq = q0 - k0;
        int adq = dq < 0 ? -dq : dq;
        bool ent = (adq <= 384);
        unsigned stb = sb + (kt & 1) * STG_SZ;

        __syncthreads();
        if (kt < 31) att_load(sb, kt + 1, q0, hoff, tid);
        if (tid < 127)
            dtab[tid] = __expf(-DECAYC * fabsf((float)(dq + tid - 63)));
        if (kt < 31) asm volatile("cp.async.wait_group 1;" ::: "memory");
        else         asm volatile("cp.async.wait_group 0;" ::: "memory");
        __syncthreads();

        float s[8][4];
#pragma unroll
        for (int j = 0; j < 8; j++)
#pragma unroll
            for (int e = 0; e < 4; e++) s[j][e] = 0.f;

        int r = 16 * w + qr;
        if (ent) {
#pragma unroll
            for (int kf = 0; kf < 4; kf++)
#pragma unroll
                for (int p = 0; p < 4; p++) {
                    unsigned t4[4];
                    ldm4(t4, stb + STG_F + boff + (unsigned)(p * 16 * 144) + kf * 32);
                    mmabf(s[2 * p], ea[kf], t4);
                    mmabf(s[2 * p + 1], ea[kf], t4 + 2);
                }
#pragma unroll
            for (int j = 0; j < 8; j++) {
                int c = 8 * j + qc;
                int b = r - c + 63;
                s[j][0] *= ENTW * dtab[b];
                s[j][1] *= ENTW * dtab[b - 1];
                s[j][2] *= ENTW * dtab[b + 8];
                s[j][3] *= ENTW * dtab[b + 7];
            }
        }
#pragma unroll
        for (int kf = 0; kf < 4; kf++)
#pragma unroll
            for (int p = 0; p < 4; p++) {
                unsigned t4[4];
                ldm4(t4, stb + STG_K + boff + (unsigned)(p * 16 * 144) + kf * 32);
                mmabf(s[2 * p], qa[kf], t4);
                mmabf(s[2 * p + 1], qa[kf], t4 + 2);
            }

        float mx0 = -1e30f, mx1 = -1e30f;
#pragma unroll
        for (int j = 0; j < 8; j++) {
            s[j][0] *= SCALE; s[j][1] *= SCALE;
            s[j][2] *= SCALE; s[j][3] *= SCALE;
            mx0 = fmaxf(mx0, fmaxf(s[j][0], s[j][1]));
            mx1 = fmaxf(mx1, fmaxf(s[j][2], s[j][3]));
        }
        mx0 = fmaxf(mx0, __shfl_xor_sync(0xffffffffu, mx0, 1));
        mx0 = fmaxf(mx0, __shfl_xor_sync(0xffffffffu, mx0, 2));
        mx1 = fmaxf(mx1, __shfl_xor_sync(0xffffffffu, mx1, 1));
        mx1 = fmaxf(mx1, __shfl_xor_sync(0xffffffffu, mx1, 2));
        float mn0 = fmaxf(m0, mx0), mn1 = fmaxf(m1, mx1);
        float al0 = __expf(m0 - mn0), al1 = __expf(m1 - mn1);
        float sum0 = 0.f, sum1 = 0.f;
        unsigned pk[8][2];
#pragma unroll
        for (int j = 0; j < 8; j++) {
            float p0 = __expf(s[j][0] - mn0);
            float p1 = __expf(s[j][1] - mn0);
            float p2 = __expf(s[j][2] - mn1);
            float p3 = __expf(s[j][3] - mn1);
            sum0 += p0 + p1; sum1 += p2 + p3;
            __nv_bfloat162 t0 = __floats2bfloat162_rn(p0, p1);
            __nv_bfloat162 t1 = __floats2bfloat162_rn(p2, p3);
            pk[j][0] = *(unsigned*)&t0;
            pk[j][1] = *(unsigned*)&t1;
        }
        sum0 += __shfl_xor_sync(0xffffffffu, sum0, 1);
        sum0 += __shfl_xor_sync(0xffffffffu, sum0, 2);
        sum1 += __shfl_xor_sync(0xffffffffu, sum1, 1);
        sum1 += __shfl_xor_sync(0xffffffffu, sum1, 2);
        l0 = l0 * al0 + sum0;
        l1 = l1 * al1 + sum1;
        m0 = mn0; m1 = mn1;

#pragma unroll
        for (int j = 0; j < 8; j++) {
            o[j][0] *= al0; o[j][1] *= al0;
            o[j][2] *= al1; o[j][3] *= al1;
        }
#pragma unroll
        for (int kf = 0; kf < 4; kf++) {
            unsigned pa4[4] = { pk[2 * kf][0], pk[2 * kf][1],
                                pk[2 * kf + 1][0], pk[2 * kf + 1][1] };
#pragma unroll
            for (int p = 0; p < 4; p++) {
                unsigned t4[4];
                ldm4(t4, stb + STG_M + boff + (unsigned)(p * 16 * 144) + kf * 32);
                mmabf(o[2 * p], pa4, t4);
                mmabf(o[2 * p + 1], pa4, t4 + 2);
            }
        }
    }

    float il0 = 1.f / l0, il1 = 1.f / l1;
    int gr = q0 + 16 * w + qr;
#pragma unroll
    for (int j = 0; j < 8; j++) {
        int c = 8 * j + qc;
        __nv_bfloat162 o0, o1;
        o0.x = __float2bfloat16(o[j][0] * il0);
        o0.y = __float2bfloat16(o[j][1] * il0);
        o1.x = __float2bfloat16(o[j][2] * il1);
        o1.y = __float2bfloat16(o[j][3] * il1);
        *(__nv_bfloat162*)(g_ab + (size_t)gr * DIM + hoff + c) = o0;
        *(__nv_bfloat162*)(g_ab + (size_t)(gr + 8) * DIM + hoff + c) = o1;
    }
}

// ---------------- K6: LayerNorm ----------------
__global__ __launch_bounds__(256) void k_ln(const float* __restrict__ g,
                                            const float* __restrict__ b,
                                            float* __restrict__ out) {
    __shared__ float s1[8], s2[8], mv[2];
    int s = blockIdx.x, tid = threadIdx.x;
    const float* r = g_res + (size_t)s * DIM;
    float4 x = *(const float4*)(r + tid * 4);
    float sum = x.x + x.y + x.z + x.w;
    float sq = x.x * x.x + x.y * x.y + x.z * x.z + x.w * x.w;
#pragma unroll
    for (int o = 16; o; o >>= 1) {
        sum += __shfl_xor_sync(0xffffffffu, sum, o);
        sq  += __shfl_xor_sync(0xffffffffu, sq, o);
    }
    if ((tid & 31) == 0) { s1[tid >> 5] = sum; s2[tid >> 5] = sq; }
    __syncthreads();
    if (tid == 0) {
        float a = 0.f, c = 0.f;
#pragma unroll
        for (int i = 0; i < 8; i++) { a += s1[i]; c += s2[i]; }
        float mean = a * (1.f / DIM);
        float var = c * (1.f / DIM) - mean * mean;
        mv[0] = mean;
        mv[1] = rsqrtf(var + LNEPS);
    }
    __syncthreads();
    float mean = mv[0], rs = mv[1];
    int c0 = tid * 4;
    float4 gg = *(const float4*)(g + c0);
    float4 bb = *(const float4*)(b + c0);
    float4 o;
    o.x = (x.x - mean) * rs * gg.x + bb.x;
    o.y = (x.y - mean) * rs * gg.y + bb.y;
    o.z = (x.z - mean) * rs * gg.z + bb.z;
    o.w = (x.w - mean) * rs * gg.w + bb.w;
    *(float4*)(out + (size_t)s * DIM + c0) = o;
}

// ---------------- launch ----------------
extern "C" void kernel_launch(void* const* d_in, const int* in_sizes, int n_in,
                              void* d_out, int out_size) {
    const float* hs  = (const float*)d_in[0];
    const float* Wq  = (const float*)d_in[1];  const float* bq  = (const float*)d_in[2];
    const float* Wk  = (const float*)d_in[3];  const float* bk  = (const float*)d_in[4];
    const float* Wv  = (const float*)d_in[5];  const float* bv  = (const float*)d_in[6];
    const float* Wo  = (const float*)d_in[7];  const float* bo  = (const float*)d_in[8];
    const float* Weq = (const float*)d_in[9];  const float* beq = (const float*)d_in[10];
    const float* Wek = (const float*)d_in[11]; const float* bek = (const float*)d_in[12];
    const float* aw  = (const float*)d_in[13]; const float* ab  = (const float*)d_in[14];
    const float* pw  = (const float*)d_in[15]; const float* pb  = (const float*)d_in[16];
    const float* mw  = (const float*)d_in[17]; const float* mb  = (const float*)d_in[18];
    const float* lg  = (const float*)d_in[19]; const float* lb  = (const float*)d_in[20];
    float* out = (float*)d_out;

    static __nv_bfloat16* wb_p = nullptr;
    static __nv_bfloat16* ab_p = nullptr;
    static cudaStream_t s2 = nullptr, s3 = nullptr;
    static cudaEvent_t evF = nullptr, evW = nullptr, evP = nullptr,
                       evV = nullptr, evM = nullptr;
    if (!wb_p) {
        cudaGetSymbolAddress((void**)&wb_p, g_wb);
        cudaGetSymbolAddress((void**)&ab_p, g_ab);
        cudaFuncSetAttribute(k_attn_tc, cudaFuncAttributeMaxDynamicSharedMemorySize,
                             ATT_SMEM);
        cudaFuncSetAttribute(k_projv, cudaFuncAttributeMaxDynamicSharedMemorySize, GSMEM);
        cudaFuncSetAttribute(k_proj4, cudaFuncAttributeMaxDynamicSharedMemorySize, GSMEM);
        cudaFuncSetAttribute(k_wo, cudaFuncAttributeMaxDynamicSharedMemorySize, GSMEM);
        cudaStreamCreateWithFlags(&s2, cudaStreamNonBlocking);
        cudaStreamCreateWithFlags(&s3, cudaStreamNonBlocking);
        cudaEventCreateWithFlags(&evF, cudaEventDisableTiming);
        cudaEventCreateWithFlags(&evW, cudaEventDisableTiming);
        cudaEventCreateWithFlags(&evP, cudaEventDisableTiming);
        cudaEventCreateWithFlags(&evV, cudaEventDisableTiming);
        cudaEventCreateWithFlags(&evM, cudaEventDisableTiming);
    }

    const int AN4 = SEQ * DIM / 4;

    // side stream s2: weight conversion, then amp/phase
    cudaEventRecord(evF, 0);
    cudaStreamWaitEvent(s2, evF, 0);
    k_cvtw<<<dim3(1024, 6), 256, 0, s2>>>(Wq, Wk, Wv, Weq, Wek, Wo, wb_p);
    cudaEventRecord(evW, s2);
    k_ampph<<<2048, 256, 0, s2>>>(hs, aw, ab, pw, pb);
    cudaEventRecord(evP, s2);

    // main stream: hs conversion -> V projection -> other projections
    k_cvt1<<<(AN4 + 255) / 256, 256>>>(hs, ab_p, AN4);
    cudaStreamWaitEvent(0, evW, 0);
    k_projv<<<dim3(8, 16), 128, GSMEM>>>(bv);
    cudaEventRecord(evV, 0);
    k_proj4<<<dim3(8, 16, 4), 128, GSMEM>>>(bq, bk, beq, bek);

    // s3: mixer overlaps the tail of k_proj4
    cudaStreamWaitEvent(s3, evV, 0);
    cudaStreamWaitEvent(s3, evP, 0);
    k_mixed<<<dim3(64, 16), 256, 0, s3>>>(mw, mb);
    cudaEventRecord(evM, s3);

    // attention after proj4 (program order) and mixer (event)
    cudaStreamWaitEvent(0, evM, 0);
    k_attn_tc<<<dim3(32, 16), 128, ATT_SMEM>>>();
    k_wo<<<dim3(8, 16), 128, GSMEM>>>(bo, hs);
    k_ln<<<2048, 256>>>(lg, lb, out);
}

// round 16
// speedup vs baseline: 1.0808x; 1.0808x over previous
#include <cuda_runtime.h>
#include <cuda_bf16.h>

#define SEQ 2048
#define DIM 1024
#define NH 16
#define HDIM 64
#define SCALE 0.125f
#define ENTW 0.5f
#define DECAYC 0.1f
#define SUPW 0.3f
#define LNEPS 1e-5f
#define PI_F 3.14159265358979323846f
#define ENT_THR 256

// ---------------- scratch ----------------
__device__ float g_v[SEQ * DIM];
__device__ float g_res[SEQ * DIM];
__device__ float g_ca[SEQ * NH];
__device__ float g_sa[SEQ * NH];
__device__ __nv_bfloat16 g_qb[SEQ * DIM];
__device__ __nv_bfloat16 g_kb[SEQ * DIM];
__device__ __nv_bfloat16 g_eqb[SEQ * DIM];
__device__ __nv_bfloat16 g_ekb[SEQ * DIM];
__device__ __nv_bfloat16 g_ab[SEQ * DIM];          // activations (hs, then ctx)
__device__ __nv_bfloat16 g_wb[6 * DIM * DIM];      // weights bf16
__device__ __nv_bfloat16 g_mxT[DIM * SEQ];         // mixed, transposed [h*64+d][s]

// ---------------- helpers ----------------
__device__ __forceinline__ unsigned smem_u32(const void* p) {
    unsigned a;
    asm("{ .reg .u64 t; cvta.to.shared.u64 t, %1; cvt.u32.u64 %0, t; }" : "=r"(a) : "l"(p));
    return a;
}
__device__ __forceinline__ void cp16(unsigned d, const void* s) {
    asm volatile("cp.async.cg.shared.global [%0], [%1], 16;" :: "r"(d), "l"(s));
}
__device__ __forceinline__ void ldm4(unsigned* r, unsigned a) {
    asm volatile("ldmatrix.sync.aligned.m8n8.x4.shared.b16 {%0,%1,%2,%3}, [%4];"
        : "=r"(r[0]), "=r"(r[1]), "=r"(r[2]), "=r"(r[3]) : "r"(a));
}
__device__ __forceinline__ void mmabf(float* d, const unsigned* a, const unsigned* b) {
    asm volatile(
        "mma.sync.aligned.m16n8k16.row.col.f32.bf16.bf16.f32 "
        "{%0,%1,%2,%3}, {%4,%5,%6,%7}, {%8,%9}, {%0,%1,%2,%3};"
        : "+f"(d[0]), "+f"(d[1]), "+f"(d[2]), "+f"(d[3])
        : "r"(a[0]), "r"(a[1]), "r"(a[2]), "r"(a[3]), "r"(b[0]), "r"(b[1]));
}

// ---------------- fp32 -> bf16 conversions ----------------
__global__ __launch_bounds__(256) void k_cvt1(const float* __restrict__ s,
                                              __nv_bfloat16* __restrict__ o, int n4) {
    int i = blockIdx.x * 256 + threadIdx.x;
    if (i >= n4) return;
    float4 x = ((const float4*)s)[i];
    __nv_bfloat162 a, b;
    a.x = __float2bfloat16(x.x); a.y = __float2bfloat16(x.y);
    b.x = __float2bfloat16(x.z); b.y = __float2bfloat16(x.w);
    ((__nv_bfloat162*)o)[i * 2] = a;
    ((__nv_bfloat162*)o)[i * 2 + 1] = b;
}

__global__ __launch_bounds__(256) void k_cvtw(
        const float* __restrict__ w0, const float* __restrict__ w1,
        const float* __restrict__ w2, const float* __restrict__ w3,
        const float* __restrict__ w4, const float* __restrict__ w5,
        __nv_bfloat16* __restrict__ o) {
    const float* src;
    switch (blockIdx.y) {
        case 0: src = w0; break;
        case 1: src = w1; break;
        case 2: src = w2; break;
        case 3: src = w3; break;
        case 4: src = w4; break;
        default: src = w5; break;
    }
    int i = blockIdx.x * 256 + threadIdx.x;
    float4 x = ((const float4*)src)[i];
    __nv_bfloat16* op = o + (size_t)blockIdx.y * DIM * DIM;
    __nv_bfloat162 a, b;
    a.x = __float2bfloat16(x.x); a.y = __float2bfloat16(x.y);
    b.x = __float2bfloat16(x.z); b.y = __float2bfloat16(x.w);
    ((__nv_bfloat162*)op)[i * 2] = a;
    ((__nv_bfloat162*)op)[i * 2 + 1] = b;
}

// ---------------- single-bf16 mma GEMM, 3-stage cp.async pipeline (R13 proven) ----
#define RSTR 40
#define PLANE 10240
#define STAGE (2 * PLANE)
#define GSMEM (3 * STAGE)          // 61440 B

__device__ __forceinline__ void load_chunk(unsigned st,
        const __nv_bfloat16* __restrict__ A, const __nv_bfloat16* __restrict__ B,
        int m0, int n0, int k0, int tid) {
#pragma unroll
    for (int i = 0; i < 4; i++) {
        int idx = i * 256 + tid;
        int plane = idx >> 9;
        int row = (idx >> 2) & 127;
        int ck = idx & 3;
        unsigned soff = st + plane * PLANE + (unsigned)(row * RSTR + ck * 8) * 2;
        const __nv_bfloat16* gp = plane
            ? (B + (size_t)(n0 + row) * DIM + k0 + ck * 8)
            : (A + (size_t)(m0 + row) * DIM + k0 + ck * 8);
        cp16(soff, gp);
    }
    asm volatile("cp.async.commit_group;" ::: "memory");
}

__device__ __forceinline__ void gemm_mma(
        const __nv_bfloat16* __restrict__ A, const __nv_bfloat16* __restrict__ W,
        const float* __restrict__ bias, const float* __restrict__ resid,
        float* __restrict__ Cf, __nv_bfloat16* __restrict__ Cb) {
    extern __shared__ char dynsm[];
    unsigned sb = smem_u32(dynsm);
    int tid = threadIdx.x, lane = tid & 31, w = tid >> 5;
    int wm = w & 1, wn = w >> 1;
    int m0 = blockIdx.y * 128, n0 = blockIdx.x * 128;

    float acc[4][4][4];
#pragma unroll
    for (int a = 0; a < 4; a++)
#pragma unroll
        for (int b = 0; b < 4; b++)
#pragma unroll
            for (int d = 0; d < 4; d++) acc[a][b][d] = 0.f;

    load_chunk(sb,          A, W, m0, n0, 0, tid);
    load_chunk(sb + STAGE,  A, W, m0, n0, 32, tid);

    int lrA = lane & 15;
    int lcA = (lane >> 4) << 3;
    int lnB = (lane & 7) + ((lane >> 4) << 3);
    int lkB = ((lane >> 3) & 1) << 3;
    unsigned aRow = (unsigned)((wm * 64 + lrA) * RSTR) * 2;
    unsigned bRow = (unsigned)((wn * 32 + lnB) * RSTR) * 2;

    int sidx = 0;
    for (int c = 0; c < 32; c++) {
        if (c < 31) asm volatile("cp.async.wait_group 1;" ::: "memory");
        else        asm volatile("cp.async.wait_group 0;" ::: "memory");
        __syncthreads();
        if (c + 2 < 32) {
            int s2i = sidx + 2; if (s2i >= 3) s2i -= 3;
            load_chunk(sb + s2i * STAGE, A, W, m0, n0, (c + 2) * 32, tid);
        }
        unsigned st = sb + sidx * STAGE;
#pragma unroll
        for (int ks = 0; ks < 32; ks += 16) {
            unsigned ah[4][4], bh[4][2];
#pragma unroll
            for (int mt = 0; mt < 4; mt++)
                ldm4(ah[mt], st + aRow + (unsigned)(mt * 16 * RSTR + ks + lcA) * 2);
#pragma unroll
            for (int p = 0; p < 2; p++) {
                unsigned t[4];
                ldm4(t, st + PLANE + bRow + (unsigned)(p * 16 * RSTR + ks + lkB) * 2);
                bh[2 * p][0] = t[0]; bh[2 * p][1] = t[1];
                bh[2 * p + 1][0] = t[2]; bh[2 * p + 1][1] = t[3];
            }
#pragma unroll
            for (int mt = 0; mt < 4; mt++)
#pragma unroll
                for (int nt = 0; nt < 4; nt++)
                    mmabf(acc[mt][nt], ah[mt], bh[nt]);
        }
        if (++sidx == 3) sidx = 0;
    }

    int r0 = m0 + wm * 64 + (lane >> 2);
    int cb = n0 + wn * 32 + (lane & 3) * 2;
#pragma unroll
    for (int mt = 0; mt < 4; mt++) {
#pragma unroll
        for (int nt = 0; nt < 4; nt++) {
            int rr = r0 + mt * 16;
            int cc = cb + nt * 8;
            float b0 = bias[cc], b1 = bias[cc + 1];
            float2 v0 = make_float2(acc[mt][nt][0] + b0, acc[mt][nt][1] + b1);
            float2 v1 = make_float2(acc[mt][nt][2] + b0, acc[mt][nt][3] + b1);
            if (resid) {
                const float2 q0 = *(const float2*)(resid + (size_t)rr * DIM + cc);
                const float2 q1 = *(const float2*)(resid + (size_t)(rr + 8) * DIM + cc);
                v0.x += q0.x; v0.y += q0.y;
                v1.x += q1.x; v1.y += q1.y;
            }
            if (Cb) {
                __nv_bfloat162 o0, o1;
                o0.x = __float2bfloat16(v0.x); o0.y = __float2bfloat16(v0.y);
                o1.x = __float2bfloat16(v1.x); o1.y = __float2bfloat16(v1.y);
                *(__nv_bfloat162*)(Cb + (size_t)rr * DIM + cc) = o0;
                *(__nv_bfloat162*)(Cb + (size_t)(rr + 8) * DIM + cc) = o1;
            } else {
                *(float2*)(Cf + (size_t)rr * DIM + cc) = v0;
                *(float2*)(Cf + (size_t)(rr + 8) * DIM + cc) = v1;
            }
        }
    }
}

__global__ __launch_bounds__(256) void k_proj5(
        const float* __restrict__ bq, const float* __restrict__ bk,
        const float* __restrict__ bv, const float* __restrict__ beq,
        const float* __restrict__ bek) {
    int z = blockIdx.z;
    const float* bias; float* Cf = nullptr; __nv_bfloat16* Cb = nullptr;
    switch (z) {
        case 0:  bias = bq;  Cb = g_qb;  break;
        case 1:  bias = bk;  Cb = g_kb;  break;
        case 2:  bias = bv;  Cf = g_v;   break;
        case 3:  bias = beq; Cb = g_eqb; break;
        default: bias = bek; Cb = g_ekb; break;
    }
    gemm_mma(g_ab, g_wb + (size_t)z * DIM * DIM, bias, nullptr, Cf, Cb);
}

__global__ __launch_bounds__(256) void k_wo(const float* __restrict__ bo,
                                            const float* __restrict__ hs) {
    gemm_mma(g_ab, g_wb + 5ull * DIM * DIM, bo, hs, g_res, nullptr);
}

// ---------------- K2: amplitudes & phases ----------------
__global__ __launch_bounds__(256) void k_ampph(const float* __restrict__ hs,
                                               const float* __restrict__ aw,
                                               const float* __restrict__ ab,
                                               const float* __restrict__ pw,
                                               const float* __restrict__ pb) {
    __shared__ float row[DIM];
    __shared__ float acc[32];
    int s = blockIdx.x, tid = threadIdx.x;
    for (int i = tid; i < DIM; i += 256) row[i] = hs[(size_t)s * DIM + i];
    __syncthreads();
    int w = tid >> 5, lane = tid & 31;
#pragma unroll
    for (int t = 0; t < 4; t++) {
        int o = w * 4 + t;
        int hh = o & 15;
        const float* wp = (o < 16) ? (aw + (size_t)hh * DIM) : (pw + (size_t)hh * DIM);
        float sum = 0.f;
        for (int i = lane; i < DIM; i += 32) sum += row[i] * wp[i];
#pragma unroll
        for (int m = 16; m; m >>= 1) sum += __shfl_xor_sync(0xffffffffu, sum, m);
        if (lane == 0) acc[o] = sum + ((o < 16) ? ab[hh] : pb[hh]);
    }
    __syncthreads();
    if (tid < NH) {
        float a = 1.f / (1.f + expf(-acc[tid]));
        float ph = tanhf(acc[16 + tid]) * PI_F;
        float sp, cp;
        sincosf(ph, &sp, &cp);
        g_ca[s * NH + tid] = SUPW * a * cp;
        g_sa[s * NH + tid] = SUPW * a * sp;
    }
}

// ---------------- K3: superposition mixer -> g_mxT ----------------
__global__ __launch_bounds__(256) void k_mixed(const float* __restrict__ mw_g,
                                               const float* __restrict__ mb_g) {
    __shared__ float mw[64][65];
    __shared__ float vt[32][65];
    __shared__ float sp[32][65];
    __shared__ float mb[64];
    int h = blockIdx.y, s0 = blockIdx.x * 32;
    int tid = threadIdx.x;
    for (int i = tid; i < 4096; i += 256) mw[i >> 6][i & 63] = mw_g[h * 4096 + i];
    if (tid < 64) mb[tid] = mb_g[h * 64 + tid];
    for (int i = tid; i < 2048; i += 256)
        vt[i >> 6][i & 63] = g_v[(size_t)(s0 + (i >> 6)) * DIM + h * HDIM + (i & 63)];
    __syncthreads();

    int r = tid >> 3;
    int ob = (tid & 7) * 8;
    float a[8];
#pragma unroll
    for (int j = 0; j < 8; j++) a[j] = 0.f;
    for (int d = 0; d < 64; d++) {
        float vv = vt[r][d];
#pragma unroll
        for (int j = 0; j < 8; j++) a[j] += vv * mw[ob + j][d];
    }
#pragma unroll
    for (int j = 0; j < 8; j++) sp[r][ob + j] = a[j] + mb[ob + j];
    __syncthreads();

    for (int i = tid; i < 2048; i += 256) {
        int d = i >> 5, sl = i & 31;
        float ca = g_ca[(s0 + sl) * NH + h];
        float sa = g_sa[(s0 + sl) * NH + h];
        float val = vt[sl][d] + ca * sp[sl][d] + sa * sp[sl][(d + 63) & 63];
        g_mxT[(size_t)(h * HDIM + d) * SEQ + s0 + sl] = __float2bfloat16(val);
    }
}

// ---------------- K4: FA2 attention, 4 CTAs/SM (R13 proven, ENT_THR=256) --------
#define STG_K 0
#define STG_M 9216
#define STG_F 18432
#define STG_SZ 27648
#define AO_D (2 * STG_SZ)
#define ATT_SMEM (2 * STG_SZ + 512)       // 55808

__device__ __forceinline__ void att_load(unsigned sb, int kt, int q0,
                                         size_t hoff, int tid) {
    int k0 = kt * 64;
    int dq = q0 - k0; int adq = dq < 0 ? -dq : dq;
    bool ent = (adq <= ENT_THR);
    unsigned st = sb + (kt & 1) * STG_SZ;
#pragma unroll
    for (int t = 0; t < 4; t++) {
        int idx = tid + t * 128;
        int row = idx >> 3, ck = idx & 7;
        cp16(st + STG_K + row * 144 + ck * 16,
             g_kb + (size_t)(k0 + row) * DIM + hoff + ck * 8);
        cp16(st + STG_M + row * 144 + ck * 16,
             g_mxT + (hoff + row) * SEQ + k0 + ck * 8);
        if (ent)
            cp16(st + STG_F + row * 144 + ck * 16,
                 g_ekb + (size_t)(k0 + row) * DIM + hoff + ck * 8);
    }
    asm volatile("cp.async.commit_group;" ::: "memory");
}

__global__ __launch_bounds__(128, 4) void k_attn_tc() {
    extern __shared__ __align__(16) char smc[];
    unsigned sb = smem_u32(smc);
    float* dtab = (float*)(smc + AO_D);

    int h = blockIdx.y, q0 = blockIdx.x * 64;
    int tid = threadIdx.x, lane = tid & 31, w = tid >> 5;
    size_t hoff = (size_t)h * HDIM;

    // prologue: Q -> stage1.K, EQ -> stage1.M (overwritten by kt=1 prefetch later)
    unsigned b1 = sb + STG_SZ;
#pragma unroll
    for (int t = 0; t < 4; t++) {
        int idx = tid + t * 128;
        int row = idx >> 3, ck = idx & 7;
        cp16(b1 + STG_K + row * 144 + ck * 16,
             g_qb + (size_t)(q0 + row) * DIM + hoff + ck * 8);
        cp16(b1 + STG_M + row * 144 + ck * 16,
             g_eqb + (size_t)(q0 + row) * DIM + hoff + ck * 8);
    }
    asm volatile("cp.async.commit_group;" ::: "memory");
    att_load(sb, 0, q0, hoff, tid);
    asm volatile("cp.async.wait_group 1;" ::: "memory");   // Q/EQ resident
    __syncthreads();

    unsigned aoff = (unsigned)((16 * w + (lane & 15)) * 144 + ((lane >> 4) << 4));
    unsigned qa[4][4], ea[4][4];
#pragma unroll
    for (int kf = 0; kf < 4; kf++) {
        ldm4(qa[kf], b1 + STG_K + aoff + kf * 32);
        ldm4(ea[kf], b1 + STG_M + aoff + kf * 32);
    }

    float m0 = -1e30f, m1 = -1e30f, l0 = 0.f, l1 = 0.f;
    float o[8][4];
#pragma unroll
    for (int j = 0; j < 8; j++)
#pragma unroll
        for (int e = 0; e < 4; e++) o[j][e] = 0.f;

    unsigned boff = (unsigned)(((lane & 7) + ((lane >> 4) << 3)) * 144 +
                               (((lane >> 3) & 1) << 4));
    int qr = (lane >> 2);
    int qc = (lane & 3) * 2;

    for (int kt = 0; kt < 32; kt++) {
        int k0 = kt * 64;
        int dq = q0 - k0;
        int adq = dq < 0 ? -dq : dq;
        bool ent = (adq <= ENT_THR);
        unsigned stb = sb + (kt & 1) * STG_SZ;

        __syncthreads();
        if (kt < 31) att_load(sb, kt + 1, q0, hoff, tid);
        if (tid < 127)
            dtab[tid] = __expf(-DECAYC * fabsf((float)(dq + tid - 63)));
        if (kt < 31) asm volatile("cp.async.wait_group 1;" ::: "memory");
        else         asm volatile("cp.async.wait_group 0;" ::: "memory");
        __syncthreads();

        // s = ENTW*decay.*(EQ EK^T), then += QK^T
        float s[8][4];
#pragma unroll
        for (int j = 0; j < 8; j++)
#pragma unroll
            for (int e = 0; e < 4; e++) s[j][e] = 0.f;

        int r = 16 * w + qr;
        if (ent) {
#pragma unroll
            for (int kf = 0; kf < 4; kf++)
#pragma unroll
                for (int p = 0; p < 4; p++) {
                    unsigned t4[4];
                    ldm4(t4, stb + STG_F + boff + (unsigned)(p * 16 * 144) + kf * 32);
                    mmabf(s[2 * p], ea[kf], t4);
                    mmabf(s[2 * p + 1], ea[kf], t4 + 2);
                }
#pragma unroll
            for (int j = 0; j < 8; j++) {
                int c = 8 * j + qc;
                int b = r - c + 63;
                s[j][0] *= ENTW * dtab[b];
                s[j][1] *= ENTW * dtab[b - 1];
                s[j][2] *= ENTW * dtab[b + 8];
                s[j][3] *= ENTW * dtab[b + 7];
            }
        }
#pragma unroll
        for (int kf = 0; kf < 4; kf++)
#pragma unroll
            for (int p = 0; p < 4; p++) {
                unsigned t4[4];
                ldm4(t4, stb + STG_K + boff + (unsigned)(p * 16 * 144) + kf * 32);
                mmabf(s[2 * p], qa[kf], t4);
                mmabf(s[2 * p + 1], qa[kf], t4 + 2);
            }

        float mx0 = -1e30f, mx1 = -1e30f;
#pragma unroll
        for (int j = 0; j < 8; j++) {
            s[j][0] *= SCALE; s[j][1] *= SCALE;
            s[j][2] *= SCALE; s[j][3] *= SCALE;
            mx0 = fmaxf(mx0, fmaxf(s[j][0], s[j][1]));
            mx1 = fmaxf(mx1, fmaxf(s[j][2], s[j][3]));
        }
        mx0 = fmaxf(mx0, __shfl_xor_sync(0xffffffffu, mx0, 1));
        mx0 = fmaxf(mx0, __shfl_xor_sync(0xffffffffu, mx0, 2));
        mx1 = fmaxf(mx1, __shfl_xor_sync(0xffffffffu, mx1, 1));
        mx1 = fmaxf(mx1, __shfl_xor_sync(0xffffffffu, mx1, 2));
        float mn0 = fmaxf(m0, mx0), mn1 = fmaxf(m1, mx1);
        float al0 = __expf(m0 - mn0), al1 = __expf(m1 - mn1);
        float sum0 = 0.f, sum1 = 0.f;
        unsigned pk[8][2];
#pragma unroll
        for (int j = 0; j < 8; j++) {
            float p0 = __expf(s[j][0] - mn0);
            float p1 = __expf(s[j][1] - mn0);
            float p2 = __expf(s[j][2] - mn1);
            float p3 = __expf(s[j][3] - mn1);
            sum0 += p0 + p1; sum1 += p2 + p3;
            __nv_bfloat162 t0 = __floats2bfloat162_rn(p0, p1);
            __nv_bfloat162 t1 = __floats2bfloat162_rn(p2, p3);
            pk[j][0] = *(unsigned*)&t0;
            pk[j][1] = *(unsigned*)&t1;
        }
        sum0 += __shfl_xor_sync(0xffffffffu, sum0, 1);
        sum0 += __shfl_xor_sync(0xffffffffu, sum0, 2);
        sum1 += __shfl_xor_sync(0xffffffffu, sum1, 1);
        sum1 += __shfl_xor_sync(0xffffffffu, sum1, 2);
        l0 = l0 * al0 + sum0;
        l1 = l1 * al1 + sum1;
        m0 = mn0; m1 = mn1;

#pragma unroll
        for (int j = 0; j < 8; j++) {
            o[j][0] *= al0; o[j][1] *= al0;
            o[j][2] *= al1; o[j][3] *= al1;
        }
#pragma unroll
        for (int kf = 0; kf < 4; kf++) {
            unsigned pa4[4] = { pk[2 * kf][0], pk[2 * kf][1],
                                pk[2 * kf + 1][0], pk[2 * kf + 1][1] };
#pragma unroll
            for (int p = 0; p < 4; p++) {
                unsigned t4[4];
                ldm4(t4, stb + STG_M + boff + (unsigned)(p * 16 * 144) + kf * 32);
                mmabf(o[2 * p], pa4, t4);
                mmabf(o[2 * p + 1], pa4, t4 + 2);
            }
        }
    }

    float il0 = 1.f / l0, il1 = 1.f / l1;
    int gr = q0 + 16 * w + qr;
#pragma unroll
    for (int j = 0; j < 8; j++) {
        int c = 8 * j + qc;
        __nv_bfloat162 o0, o1;
        o0.x = __float2bfloat16(o[j][0] * il0);
        o0.y = __float2bfloat16(o[j][1] * il0);
        o1.x = __float2bfloat16(o[j][2] * il1);
        o1.y = __float2bfloat16(o[j][3] * il1);
        *(__nv_bfloat162*)(g_ab + (size_t)gr * DIM + hoff + c) = o0;
        *(__nv_bfloat162*)(g_ab + (size_t)(gr + 8) * DIM + hoff + c) = o1;
    }
}

// ---------------- K6: LayerNorm ----------------
__global__ __launch_bounds__(256) void k_ln(const float* __restrict__ g,
                                            const float* __restrict__ b,
                                            float* __restrict__ out) {
    __shared__ float s1[8], s2[8], mv[2];
    int s = blockIdx.x, tid = threadIdx.x;
    const float* r = g_res + (size_t)s * DIM;
    float4 x = *(const float4*)(r + tid * 4);
    float sum = x.x + x.y + x.z + x.w;
    float sq = x.x * x.x + x.y * x.y + x.z * x.z + x.w * x.w;
#pragma unroll
    for (int o = 16; o; o >>= 1) {
        sum += __shfl_xor_sync(0xffffffffu, sum, o);
        sq  += __shfl_xor_sync(0xffffffffu, sq, o);
    }
    if ((tid & 31) == 0) { s1[tid >> 5] = sum; s2[tid >> 5] = sq; }
    __syncthreads();
    if (tid == 0) {
        float a = 0.f, c = 0.f;
#pragma unroll
        for (int i = 0; i < 8; i++) { a += s1[i]; c += s2[i]; }
        float mean = a * (1.f / DIM);
        float var = c * (1.f / DIM) - mean * mean;
        mv[0] = mean;
        mv[1] = rsqrtf(var + LNEPS);
    }
    __syncthreads();
    float mean = mv[0], rs = mv[1];
    int c0 = tid * 4;
    float4 gg = *(const float4*)(g + c0);
    float4 bb = *(const float4*)(b + c0);
    float4 o;
    o.x = (x.x - mean) * rs * gg.x + bb.x;
    o.y = (x.y - mean) * rs * gg.y + bb.y;
    o.z = (x.z - mean) * rs * gg.z + bb.z;
    o.w = (x.w - mean) * rs * gg.w + bb.w;
    *(float4*)(out + (size_t)s * DIM + c0) = o;
}

// ---------------- launch (R13 proven schedule) ----------------
extern "C" void kernel_launch(void* const* d_in, const int* in_sizes, int n_in,
                              void* d_out, int out_size) {
    const float* hs  = (const float*)d_in[0];
    const float* Wq  = (const float*)d_in[1];  const float* bq  = (const float*)d_in[2];
    const float* Wk  = (const float*)d_in[3];  const float* bk  = (const float*)d_in[4];
    const float* Wv  = (const float*)d_in[5];  const float* bv  = (const float*)d_in[6];
    const float* Wo  = (const float*)d_in[7];  const float* bo  = (const float*)d_in[8];
    const float* Weq = (const float*)d_in[9];  const float* beq = (const float*)d_in[10];
    const float* Wek = (const float*)d_in[11]; const float* bek = (const float*)d_in[12];
    const float* aw  = (const float*)d_in[13]; const float* ab  = (const float*)d_in[14];
    const float* pw  = (const float*)d_in[15]; const float* pb  = (const float*)d_in[16];
    const float* mw  = (const float*)d_in[17]; const float* mb  = (const float*)d_in[18];
    const float* lg  = (const float*)d_in[19]; const float* lb  = (const float*)d_in[20];
    float* out = (float*)d_out;

    static __nv_bfloat16* wb_p = nullptr;
    static __nv_bfloat16* ab_p = nullptr;
    static cudaStream_t s2 = nullptr;
    static cudaEvent_t evF = nullptr, evW = nullptr, evP = nullptr;
    if (!wb_p) {
        cudaGetSymbolAddress((void**)&wb_p, g_wb);
        cudaGetSymbolAddress((void**)&ab_p, g_ab);
        cudaFuncSetAttribute(k_attn_tc, cudaFuncAttributeMaxDynamicSharedMemorySize,
                             ATT_SMEM);
        cudaFuncSetAttribute(k_proj5, cudaFuncAttributeMaxDynamicSharedMemorySize, GSMEM);
        cudaFuncSetAttribute(k_wo, cudaFuncAttributeMaxDynamicSharedMemorySize, GSMEM);
        cudaStreamCreateWithFlags(&s2, cudaStreamNonBlocking);
        cudaEventCreateWithFlags(&evF, cudaEventDisableTiming);
        cudaEventCreateWithFlags(&evW, cudaEventDisableTiming);
        cudaEventCreateWithFlags(&evP, cudaEventDisableTiming);
    }

    const int AN4 = SEQ * DIM / 4;

    // side stream: weight conversion, then amp/phase (depends only on hs)
    cudaEventRecord(evF, 0);
    cudaStreamWaitEvent(s2, evF, 0);
    k_cvtw<<<dim3(1024, 6), 256, 0, s2>>>(Wq, Wk, Wv, Weq, Wek, Wo, wb_p);
    cudaEventRecord(evW, s2);
    k_ampph<<<2048, 256, 0, s2>>>(hs, aw, ab, pw, pb);
    cudaEventRecord(evP, s2);

    // main stream
    k_cvt1<<<(AN4 + 255) / 256, 256>>>(hs, ab_p, AN4);
    cudaStreamWaitEvent(0, evW, 0);
    k_proj5<<<dim3(8, 16, 5), 256, GSMEM>>>(bq, bk, bv, beq, bek);
    cudaStreamWaitEvent(0, evP, 0);
    k_mixed<<<dim3(64, 16), 256>>>(mw, mb);
    k_attn_tc<<<dim3(32, 16), 128, ATT_SMEM>>>();
    k_wo<<<dim3(8, 16), 256, GSMEM>>>(bo, hs);
    k_ln<<<2048, 256>>>(lg, lb, out);
}

// round 17
// speedup vs baseline: 1.1106x; 1.0275x over previous
#include <cuda_runtime.h>
#include <cuda_bf16.h>

#define SEQ 2048
#define DIM 1024
#define NH 16
#define HDIM 64
#define SCALE 0.125f
#define ENTW 0.5f
#define DECAYC 0.1f
#define SUPW 0.3f
#define LNEPS 1e-5f
#define PI_F 3.14159265358979323846f
#define ENT_THR 256

// ---------------- scratch ----------------
__device__ float g_v[SEQ * DIM];
__device__ float g_res[SEQ * DIM];
__device__ float g_ca[SEQ * NH];
__device__ float g_sa[SEQ * NH];
__device__ __nv_bfloat16 g_qb[SEQ * DIM];
__device__ __nv_bfloat16 g_kb[SEQ * DIM];
__device__ __nv_bfloat16 g_eqb[SEQ * DIM];
__device__ __nv_bfloat16 g_ekb[SEQ * DIM];
__device__ __nv_bfloat16 g_ab[SEQ * DIM];          // activations (hs, then ctx)
__device__ __nv_bfloat16 g_wb[6 * DIM * DIM];      // weights bf16
__device__ __nv_bfloat16 g_mxT[DIM * SEQ];         // mixed, transposed [h*64+d][s]

// ---------------- helpers ----------------
__device__ __forceinline__ unsigned smem_u32(const void* p) {
    unsigned a;
    asm("{ .reg .u64 t; cvta.to.shared.u64 t, %1; cvt.u32.u64 %0, t; }" : "=r"(a) : "l"(p));
    return a;
}
__device__ __forceinline__ void cp16(unsigned d, const void* s) {
    asm volatile("cp.async.cg.shared.global [%0], [%1], 16;" :: "r"(d), "l"(s));
}
__device__ __forceinline__ void ldm4(unsigned* r, unsigned a) {
    asm volatile("ldmatrix.sync.aligned.m8n8.x4.shared.b16 {%0,%1,%2,%3}, [%4];"
        : "=r"(r[0]), "=r"(r[1]), "=r"(r[2]), "=r"(r[3]) : "r"(a));
}
__device__ __forceinline__ void mmabf(float* d, const unsigned* a, const unsigned* b) {
    asm volatile(
        "mma.sync.aligned.m16n8k16.row.col.f32.bf16.bf16.f32 "
        "{%0,%1,%2,%3}, {%4,%5,%6,%7}, {%8,%9}, {%0,%1,%2,%3};"
        : "+f"(d[0]), "+f"(d[1]), "+f"(d[2]), "+f"(d[3])
        : "r"(a[0]), "r"(a[1]), "r"(a[2]), "r"(a[3]), "r"(b[0]), "r"(b[1]));
}

// ---------------- fp32 -> bf16 conversions ----------------
__global__ __launch_bounds__(256) void k_cvt1(const float* __restrict__ s,
                                              __nv_bfloat16* __restrict__ o, int n4) {
    int i = blockIdx.x * 256 + threadIdx.x;
    if (i >= n4) return;
    float4 x = ((const float4*)s)[i];
    __nv_bfloat162 a, b;
    a.x = __float2bfloat16(x.x); a.y = __float2bfloat16(x.y);
    b.x = __float2bfloat16(x.z); b.y = __float2bfloat16(x.w);
    ((__nv_bfloat162*)o)[i * 2] = a;
    ((__nv_bfloat162*)o)[i * 2 + 1] = b;
}

__global__ __launch_bounds__(256) void k_cvtw(
        const float* __restrict__ w0, const float* __restrict__ w1,
        const float* __restrict__ w2, const float* __restrict__ w3,
        const float* __restrict__ w4, const float* __restrict__ w5,
        __nv_bfloat16* __restrict__ o) {
    const float* src;
    switch (blockIdx.y) {
        case 0: src = w0; break;
        case 1: src = w1; break;
        case 2: src = w2; break;
        case 3: src = w3; break;
        case 4: src = w4; break;
        default: src = w5; break;
    }
    int i = blockIdx.x * 256 + threadIdx.x;
    float4 x = ((const float4*)src)[i];
    __nv_bfloat16* op = o + (size_t)blockIdx.y * DIM * DIM;
    __nv_bfloat162 a, b;
    a.x = __float2bfloat16(x.x); a.y = __float2bfloat16(x.y);
    b.x = __float2bfloat16(x.z); b.y = __float2bfloat16(x.w);
    ((__nv_bfloat162*)op)[i * 2] = a;
    ((__nv_bfloat162*)op)[i * 2 + 1] = b;
}

// ---------------- single-bf16 mma GEMM, 3-stage cp.async pipeline (proven) ----
#define RSTR 40
#define PLANE 10240
#define STAGE (2 * PLANE)
#define GSMEM (3 * STAGE)          // 61440 B

__device__ __forceinline__ void load_chunk(unsigned st,
        const __nv_bfloat16* __restrict__ A, const __nv_bfloat16* __restrict__ B,
        int m0, int n0, int k0, int tid) {
#pragma unroll
    for (int i = 0; i < 4; i++) {
        int idx = i * 256 + tid;
        int plane = idx >> 9;
        int row = (idx >> 2) & 127;
        int ck = idx & 3;
        unsigned soff = st + plane * PLANE + (unsigned)(row * RSTR + ck * 8) * 2;
        const __nv_bfloat16* gp = plane
            ? (B + (size_t)(n0 + row) * DIM + k0 + ck * 8)
            : (A + (size_t)(m0 + row) * DIM + k0 + ck * 8);
        cp16(soff, gp);
    }
    asm volatile("cp.async.commit_group;" ::: "memory");
}

__device__ __forceinline__ void gemm_mma(
        const __nv_bfloat16* __restrict__ A, const __nv_bfloat16* __restrict__ W,
        const float* __restrict__ bias, const float* __restrict__ resid,
        float* __restrict__ Cf, __nv_bfloat16* __restrict__ Cb) {
    extern __shared__ char dynsm[];
    unsigned sb = smem_u32(dynsm);
    int tid = threadIdx.x, lane = tid & 31, w = tid >> 5;
    int wm = w & 1, wn = w >> 1;
    int m0 = blockIdx.y * 128, n0 = blockIdx.x * 128;

    float acc[4][4][4];
#pragma unroll
    for (int a = 0; a < 4; a++)
#pragma unroll
        for (int b = 0; b < 4; b++)
#pragma unroll
            for (int d = 0; d < 4; d++) acc[a][b][d] = 0.f;

    load_chunk(sb,          A, W, m0, n0, 0, tid);
    load_chunk(sb + STAGE,  A, W, m0, n0, 32, tid);

    int lrA = lane & 15;
    int lcA = (lane >> 4) << 3;
    int lnB = (lane & 7) + ((lane >> 4) << 3);
    int lkB = ((lane >> 3) & 1) << 3;
    unsigned aRow = (unsigned)((wm * 64 + lrA) * RSTR) * 2;
    unsigned bRow = (unsigned)((wn * 32 + lnB) * RSTR) * 2;

    int sidx = 0;
    for (int c = 0; c < 32; c++) {
        if (c < 31) asm volatile("cp.async.wait_group 1;" ::: "memory");
        else        asm volatile("cp.async.wait_group 0;" ::: "memory");
        __syncthreads();
        if (c + 2 < 32) {
            int s2i = sidx + 2; if (s2i >= 3) s2i -= 3;
            load_chunk(sb + s2i * STAGE, A, W, m0, n0, (c + 2) * 32, tid);
        }
        unsigned st = sb + sidx * STAGE;
#pragma unroll
        for (int ks = 0; ks < 32; ks += 16) {
            unsigned ah[4][4], bh[4][2];
#pragma unroll
            for (int mt = 0; mt < 4; mt++)
                ldm4(ah[mt], st + aRow + (unsigned)(mt * 16 * RSTR + ks + lcA) * 2);
#pragma unroll
            for (int p = 0; p < 2; p++) {
                unsigned t[4];
                ldm4(t, st + PLANE + bRow + (unsigned)(p * 16 * RSTR + ks + lkB) * 2);
                bh[2 * p][0] = t[0]; bh[2 * p][1] = t[1];
                bh[2 * p + 1][0] = t[2]; bh[2 * p + 1][1] = t[3];
            }
#pragma unroll
            for (int mt = 0; mt < 4; mt++)
#pragma unroll
                for (int nt = 0; nt < 4; nt++)
                    mmabf(acc[mt][nt], ah[mt], bh[nt]);
        }
        if (++sidx == 3) sidx = 0;
    }

    int r0 = m0 + wm * 64 + (lane >> 2);
    int cb = n0 + wn * 32 + (lane & 3) * 2;
#pragma unroll
    for (int mt = 0; mt < 4; mt++) {
#pragma unroll
        for (int nt = 0; nt < 4; nt++) {
            int rr = r0 + mt * 16;
            int cc = cb + nt * 8;
            float b0 = bias[cc], b1 = bias[cc + 1];
            float2 v0 = make_float2(acc[mt][nt][0] + b0, acc[mt][nt][1] + b1);
            float2 v1 = make_float2(acc[mt][nt][2] + b0, acc[mt][nt][3] + b1);
            if (resid) {
                const float2 q0 = *(const float2*)(resid + (size_t)rr * DIM + cc);
                const float2 q1 = *(const float2*)(resid + (size_t)(rr + 8) * DIM + cc);
                v0.x += q0.x; v0.y += q0.y;
                v1.x += q1.x; v1.y += q1.y;
            }
            if (Cb) {
                __nv_bfloat162 o0, o1;
                o0.x = __float2bfloat16(v0.x); o0.y = __float2bfloat16(v0.y);
                o1.x = __float2bfloat16(v1.x); o1.y = __float2bfloat16(v1.y);
                *(__nv_bfloat162*)(Cb + (size_t)rr * DIM + cc) = o0;
                *(__nv_bfloat162*)(Cb + (size_t)(rr + 8) * DIM + cc) = o1;
            } else {
                *(float2*)(Cf + (size_t)rr * DIM + cc) = v0;
                *(float2*)(Cf + (size_t)(rr + 8) * DIM + cc) = v1;
            }
        }
    }
}

__global__ __launch_bounds__(256) void k_proj5(
        const float* __restrict__ bq, const float* __restrict__ bk,
        const float* __restrict__ bv, const float* __restrict__ beq,
        const float* __restrict__ bek) {
    int z = blockIdx.z;
    const float* bias; float* Cf = nullptr; __nv_bfloat16* Cb = nullptr;
    switch (z) {
        case 0:  bias = bq;  Cb = g_qb;  break;
        case 1:  bias = bk;  Cb = g_kb;  break;
        case 2:  bias = bv;  Cf = g_v;   break;
        case 3:  bias = beq; Cb = g_eqb; break;
        default: bias = bek; Cb = g_ekb; break;
    }
    gemm_mma(g_ab, g_wb + (size_t)z * DIM * DIM, bias, nullptr, Cf, Cb);
}

__global__ __launch_bounds__(256) void k_wo(const float* __restrict__ bo,
                                            const float* __restrict__ hs) {
    gemm_mma(g_ab, g_wb + 5ull * DIM * DIM, bo, hs, g_res, nullptr);
}

// ---------------- K2: amplitudes & phases ----------------
__global__ __launch_bounds__(256) void k_ampph(const float* __restrict__ hs,
                                               const float* __restrict__ aw,
                                               const float* __restrict__ ab,
                                               const float* __restrict__ pw,
                                               const float* __restrict__ pb) {
    __shared__ float row[DIM];
    __shared__ float acc[32];
    int s = blockIdx.x, tid = threadIdx.x;
    for (int i = tid; i < DIM; i += 256) row[i] = hs[(size_t)s * DIM + i];
    __syncthreads();
    int w = tid >> 5, lane = tid & 31;
#pragma unroll
    for (int t = 0; t < 4; t++) {
        int o = w * 4 + t;
        int hh = o & 15;
        const float* wp = (o < 16) ? (aw + (size_t)hh * DIM) : (pw + (size_t)hh * DIM);
        float sum = 0.f;
        for (int i = lane; i < DIM; i += 32) sum += row[i] * wp[i];
#pragma unroll
        for (int m = 16; m; m >>= 1) sum += __shfl_xor_sync(0xffffffffu, sum, m);
        if (lane == 0) acc[o] = sum + ((o < 16) ? ab[hh] : pb[hh]);
    }
    __syncthreads();
    if (tid < NH) {
        float a = 1.f / (1.f + expf(-acc[tid]));
        float ph = tanhf(acc[16 + tid]) * PI_F;
        float sp, cp;
        sincosf(ph, &sp, &cp);
        g_ca[s * NH + tid] = SUPW * a * cp;
        g_sa[s * NH + tid] = SUPW * a * sp;
    }
}

// ---------------- K3: superposition mixer -> g_mxT ----------------
__global__ __launch_bounds__(256) void k_mixed(const float* __restrict__ mw_g,
                                               const float* __restrict__ mb_g) {
    __shared__ float mw[64][65];
    __shared__ float vt[32][65];
    __shared__ float sp[32][65];
    __shared__ float mb[64];
    int h = blockIdx.y, s0 = blockIdx.x * 32;
    int tid = threadIdx.x;
    for (int i = tid; i < 4096; i += 256) mw[i >> 6][i & 63] = mw_g[h * 4096 + i];
    if (tid < 64) mb[tid] = mb_g[h * 64 + tid];
    for (int i = tid; i < 2048; i += 256)
        vt[i >> 6][i & 63] = g_v[(size_t)(s0 + (i >> 6)) * DIM + h * HDIM + (i & 63)];
    __syncthreads();

    int r = tid >> 3;
    int ob = (tid & 7) * 8;
    float a[8];
#pragma unroll
    for (int j = 0; j < 8; j++) a[j] = 0.f;
    for (int d = 0; d < 64; d++) {
        float vv = vt[r][d];
#pragma unroll
        for (int j = 0; j < 8; j++) a[j] += vv * mw[ob + j][d];
    }
#pragma unroll
    for (int j = 0; j < 8; j++) sp[r][ob + j] = a[j] + mb[ob + j];
    __syncthreads();

    for (int i = tid; i < 2048; i += 256) {
        int d = i >> 5, sl = i & 31;
        float ca = g_ca[(s0 + sl) * NH + h];
        float sa = g_sa[(s0 + sl) * NH + h];
        float val = vt[sl][d] + ca * sp[sl][d] + sa * sp[sl][(d + 63) & 63];
        g_mxT[(size_t)(h * HDIM + d) * SEQ + s0 + sl] = __float2bfloat16(val);
    }
}

// ---------------- K4: FA2 attention, q-tile 128 (8 warps), 2 CTAs/SM ----------
#define STG_K 0
#define STG_M 9216
#define STG_F 18432
#define STG_SZ 27648
#define AO_Q 0
#define AO_E 18432
#define AO_ST 36864
#define AO_D (AO_ST + 2 * STG_SZ)         // 92160, dtab 192 floats
#define ATT_SMEM (AO_D + 768)             // 92928

__device__ __forceinline__ bool ent_tile(int dq) {
    return (dq <= ENT_THR) && (dq >= -(ENT_THR + 64));
}

__device__ __forceinline__ void att_load(unsigned sb, int kt, int q0,
                                         size_t hoff, int tid) {
    int k0 = kt * 64;
    int dq = q0 - k0;
    bool ent = ent_tile(dq);
    unsigned st = sb + AO_ST + (kt & 1) * STG_SZ;
#pragma unroll
    for (int t = 0; t < 2; t++) {
        int idx = tid + t * 256;           // 0..511
        int row = idx >> 3, ck = idx & 7;
        cp16(st + STG_K + row * 144 + ck * 16,
             g_kb + (size_t)(k0 + row) * DIM + hoff + ck * 8);
        cp16(st + STG_M + row * 144 + ck * 16,
             g_mxT + (hoff + row) * SEQ + k0 + ck * 8);
        if (ent)
            cp16(st + STG_F + row * 144 + ck * 16,
                 g_ekb + (size_t)(k0 + row) * DIM + hoff + ck * 8);
    }
    asm volatile("cp.async.commit_group;" ::: "memory");
}

__global__ __launch_bounds__(256, 2) void k_attn_tc() {
    extern __shared__ __align__(16) char smc[];
    unsigned sb = smem_u32(smc);
    float* dtab = (float*)(smc + AO_D);

    int h = blockIdx.y, q0 = blockIdx.x * 128;
    int tid = threadIdx.x, lane = tid & 31, w = tid >> 5;   // 8 warps, 16 rows each
    size_t hoff = (size_t)h * HDIM;

    // prologue: Q/EQ tiles (128 rows x 64 bf16)
#pragma unroll
    for (int t = 0; t < 4; t++) {
        int idx = tid + t * 256;           // 0..1023
        int row = idx >> 3, ck = idx & 7;
        cp16(sb + AO_Q + row * 144 + ck * 16,
             g_qb + (size_t)(q0 + row) * DIM + hoff + ck * 8);
        cp16(sb + AO_E + row * 144 + ck * 16,
             g_eqb + (size_t)(q0 + row) * DIM + hoff + ck * 8);
    }
    asm volatile("cp.async.commit_group;" ::: "memory");
    att_load(sb, 0, q0, hoff, tid);
    asm volatile("cp.async.wait_group 1;" ::: "memory");   // Q/EQ resident
    __syncthreads();

    // cache Q/EQ A-fragments in registers
    unsigned aoff = (unsigned)((16 * w + (lane & 15)) * 144 + ((lane >> 4) << 4));
    unsigned qa[4][4], ea[4][4];
#pragma unroll
    for (int kf = 0; kf < 4; kf++) {
        ldm4(qa[kf], sb + AO_Q + aoff + kf * 32);
        ldm4(ea[kf], sb + AO_E + aoff + kf * 32);
    }

    float m0 = -1e30f, m1 = -1e30f, l0 = 0.f, l1 = 0.f;
    float o[8][4];
#pragma unroll
    for (int j = 0; j < 8; j++)
#pragma unroll
        for (int e = 0; e < 4; e++) o[j][e] = 0.f;

    unsigned boff = (unsigned)(((lane & 7) + ((lane >> 4) << 3)) * 144 +
                               (((lane >> 3) & 1) << 4));
    int qr = (lane >> 2);
    int qc = (lane & 3) * 2;

    for (int kt = 0; kt < 32; kt++) {
        int k0 = kt * 64;
        int dq = q0 - k0;
        bool ent = ent_tile(dq);
        unsigned stb = sb + AO_ST + (kt & 1) * STG_SZ;

        __syncthreads();
        if (kt < 31) att_load(sb, kt + 1, q0, hoff, tid);
        if (tid < 191)
            dtab[tid] = __expf(-DECAYC * fabsf((float)(dq + tid - 63)));
        if (kt < 31) asm volatile("cp.async.wait_group 1;" ::: "memory");
        else         asm volatile("cp.async.wait_group 0;" ::: "memory");
        __syncthreads();

        // s = ENTW*decay.*(EQ EK^T), then += QK^T
        float s[8][4];
#pragma unroll
        for (int j = 0; j < 8; j++)
#pragma unroll
            for (int e = 0; e < 4; e++) s[j][e] = 0.f;

        int r = 16 * w + qr;
        if (ent) {
#pragma unroll
            for (int kf = 0; kf < 4; kf++)
#pragma unroll
                for (int p = 0; p < 4; p++) {
                    unsigned t4[4];
                    ldm4(t4, stb + STG_F + boff + (unsigned)(p * 16 * 144) + kf * 32);
                    mmabf(s[2 * p], ea[kf], t4);
                    mmabf(s[2 * p + 1], ea[kf], t4 + 2);
                }
#pragma unroll
            for (int j = 0; j < 8; j++) {
                int c = 8 * j + qc;
                int b = r - c + 63;
                s[j][0] *= ENTW * dtab[b];
                s[j][1] *= ENTW * dtab[b - 1];
                s[j][2] *= ENTW * dtab[b + 8];
                s[j][3] *= ENTW * dtab[b + 7];
            }
        }
#pragma unroll
        for (int kf = 0; kf < 4; kf++)
#pragma unroll
            for (int p = 0; p < 4; p++) {
                unsigned t4[4];
                ldm4(t4, stb + STG_K + boff + (unsigned)(p * 16 * 144) + kf * 32);
                mmabf(s[2 * p], qa[kf], t4);
                mmabf(s[2 * p + 1], qa[kf], t4 + 2);
            }

        float mx0 = -1e30f, mx1 = -1e30f;
#pragma unroll
        for (int j = 0; j < 8; j++) {
            s[j][0] *= SCALE; s[j][1] *= SCALE;
            s[j][2] *= SCALE; s[j][3] *= SCALE;
            mx0 = fmaxf(mx0, fmaxf(s[j][0], s[j][1]));
            mx1 = fmaxf(mx1, fmaxf(s[j][2], s[j][3]));
        }
        mx0 = fmaxf(mx0, __shfl_xor_sync(0xffffffffu, mx0, 1));
        mx0 = fmaxf(mx0, __shfl_xor_sync(0xffffffffu, mx0, 2));
        mx1 = fmaxf(mx1, __shfl_xor_sync(0xffffffffu, mx1, 1));
        mx1 = fmaxf(mx1, __shfl_xor_sync(0xffffffffu, mx1, 2));
        float mn0 = fmaxf(m0, mx0), mn1 = fmaxf(m1, mx1);
        float al0 = __expf(m0 - mn0), al1 = __expf(m1 - mn1);
        float sum0 = 0.f, sum1 = 0.f;
        unsigned pk[8][2];
#pragma unroll
        for (int j = 0; j < 8; j++) {
            float p0 = __expf(s[j][0] - mn0);
            float p1 = __expf(s[j][1] - mn0);
            float p2 = __expf(s[j][2] - mn1);
            float p3 = __expf(s[j][3] - mn1);
            sum0 += p0 + p1; sum1 += p2 + p3;
            __nv_bfloat162 t0 = __floats2bfloat162_rn(p0, p1);
            __nv_bfloat162 t1 = __floats2bfloat162_rn(p2, p3);
            pk[j][0] = *(unsigned*)&t0;
            pk[j][1] = *(unsigned*)&t1;
        }
        sum0 += __shfl_xor_sync(0xffffffffu, sum0, 1);
        sum0 += __shfl_xor_sync(0xffffffffu, sum0, 2);
        sum1 += __shfl_xor_sync(0xffffffffu, sum1, 1);
        sum1 += __shfl_xor_sync(0xffffffffu, sum1, 2);
        l0 = l0 * al0 + sum0;
        l1 = l1 * al1 + sum1;
        m0 = mn0; m1 = mn1;

#pragma unroll
        for (int j = 0; j < 8; j++) {
            o[j][0] *= al0; o[j][1] *= al0;
            o[j][2] *= al1; o[j][3] *= al1;
        }
#pragma unroll
        for (int kf = 0; kf < 4; kf++) {
            unsigned pa4[4] = { pk[2 * kf][0], pk[2 * kf][1],
                                pk[2 * kf + 1][0], pk[2 * kf + 1][1] };
#pragma unroll
            for (int p = 0; p < 4; p++) {
                unsigned t4[4];
                ldm4(t4, stb + STG_M + boff + (unsigned)(p * 16 * 144) + kf * 32);
                mmabf(o[2 * p], pa4, t4);
                mmabf(o[2 * p + 1], pa4, t4 + 2);
            }
        }
    }

    float il0 = 1.f / l0, il1 = 1.f / l1;
    int gr = q0 + 16 * w + qr;
#pragma unroll
    for (int j = 0; j < 8; j++) {
        int c = 8 * j + qc;
        __nv_bfloat162 o0, o1;
        o0.x = __float2bfloat16(o[j][0] * il0);
        o0.y = __float2bfloat16(o[j][1] * il0);
        o1.x = __float2bfloat16(o[j][2] * il1);
        o1.y = __float2bfloat16(o[j][3] * il1);
        *(__nv_bfloat162*)(g_ab + (size_t)gr * DIM + hoff + c) = o0;
        *(__nv_bfloat162*)(g_ab + (size_t)(gr + 8) * DIM + hoff + c) = o1;
    }
}

// ---------------- K6: LayerNorm ----------------
__global__ __launch_bounds__(256) void k_ln(const float* __restrict__ g,
                                            const float* __restrict__ b,
                                            float* __restrict__ out) {
    __shared__ float s1[8], s2[8], mv[2];
    int s = blockIdx.x, tid = threadIdx.x;
    const float* r = g_res + (size_t)s * DIM;
    float4 x = *(const float4*)(r + tid * 4);
    float sum = x.x + x.y + x.z + x.w;
    float sq = x.x * x.x + x.y * x.y + x.z * x.z + x.w * x.w;
#pragma unroll
    for (int o = 16; o; o >>= 1) {
        sum += __shfl_xor_sync(0xffffffffu, sum, o);
        sq  += __shfl_xor_sync(0xffffffffu, sq, o);
    }
    if ((tid & 31) == 0) { s1[tid >> 5] = sum; s2[tid >> 5] = sq; }
    __syncthreads();
    if (tid == 0) {
        float a = 0.f, c = 0.f;
#pragma unroll
        for (int i = 0; i < 8; i++) { a += s1[i]; c += s2[i]; }
        float mean = a * (1.f / DIM);
        float var = c * (1.f / DIM) - mean * mean;
        mv[0] = mean;
        mv[1] = rsqrtf(var + LNEPS);
    }
    __syncthreads();
    float mean = mv[0], rs = mv[1];
    int c0 = tid * 4;
    float4 gg = *(const float4*)(g + c0);
    float4 bb = *(const float4*)(b + c0);
    float4 o;
    o.x = (x.x - mean) * rs * gg.x + bb.x;
    o.y = (x.y - mean) * rs * gg.y + bb.y;
    o.z = (x.z - mean) * rs * gg.z + bb.z;
    o.w = (x.w - mean) * rs * gg.w + bb.w;
    *(float4*)(out + (size_t)s * DIM + c0) = o;
}

// ---------------- launch ----------------
extern "C" void kernel_launch(void* const* d_in, const int* in_sizes, int n_in,
                              void* d_out, int out_size) {
    const float* hs  = (const float*)d_in[0];
    const float* Wq  = (const float*)d_in[1];  const float* bq  = (const float*)d_in[2];
    const float* Wk  = (const float*)d_in[3];  const float* bk  = (const float*)d_in[4];
    const float* Wv  = (const float*)d_in[5];  const float* bv  = (const float*)d_in[6];
    const float* Wo  = (const float*)d_in[7];  const float* bo  = (const float*)d_in[8];
    const float* Weq = (const float*)d_in[9];  const float* beq = (const float*)d_in[10];
    const float* Wek = (const float*)d_in[11]; const float* bek = (const float*)d_in[12];
    const float* aw  = (const float*)d_in[13]; const float* ab  = (const float*)d_in[14];
    const float* pw  = (const float*)d_in[15]; const float* pb  = (const float*)d_in[16];
    const float* mw  = (const float*)d_in[17]; const float* mb  = (const float*)d_in[18];
    const float* lg  = (const float*)d_in[19]; const float* lb  = (const float*)d_in[20];
    float* out = (float*)d_out;

    static __nv_bfloat16* wb_p = nullptr;
    static __nv_bfloat16* ab_p = nullptr;
    static cudaStream_t s2 = nullptr;
    static cudaEvent_t evF = nullptr, evW = nullptr, evP = nullptr;
    if (!wb_p) {
        cudaGetSymbolAddress((void**)&wb_p, g_wb);
        cudaGetSymbolAddress((void**)&ab_p, g_ab);
        cudaFuncSetAttribute(k_attn_tc, cudaFuncAttributeMaxDynamicSharedMemorySize,
                             ATT_SMEM);
        cudaFuncSetAttribute(k_proj5, cudaFuncAttributeMaxDynamicSharedMemorySize, GSMEM);
        cudaFuncSetAttribute(k_wo, cudaFuncAttributeMaxDynamicSharedMemorySize, GSMEM);
        cudaStreamCreateWithFlags(&s2, cudaStreamNonBlocking);
        cudaEventCreateWithFlags(&evF, cudaEventDisableTiming);
        cudaEventCreateWithFlags(&evW, cudaEventDisableTiming);
        cudaEventCreateWithFlags(&evP, cudaEventDisableTiming);
    }

    const int AN4 = SEQ * DIM / 4;

    // side stream: weight conversion, then amp/phase (depends only on hs)
    cudaEventRecord(evF, 0);
    cudaStreamWaitEvent(s2, evF, 0);
    k_cvtw<<<dim3(1024, 6), 256, 0, s2>>>(Wq, Wk, Wv, Weq, Wek, Wo, wb_p);
    cudaEventRecord(evW, s2);
    k_ampph<<<2048, 256, 0, s2>>>(hs, aw, ab, pw, pb);
    cudaEventRecord(evP, s2);

    // main stream
    k_cvt1<<<(AN4 + 255) / 256, 256>>>(hs, ab_p, AN4);
    cudaStreamWaitEvent(0, evW, 0);
    k_proj5<<<dim3(8, 16, 5), 256, GSMEM>>>(bq, bk, bv, beq, bek);
    cudaStreamWaitEvent(0, evP, 0);
    k_mixed<<<dim3(64, 16), 256>>>(mw, mb);
    k_attn_tc<<<dim3(16, 16), 256, ATT_SMEM>>>();
    k_wo<<<dim3(8, 16), 256, GSMEM>>>(bo, hs);
    k_ln<<<2048, 256>>>(lg, lb, out);
}